// round 14
// baseline (speedup 1.0000x reference)
#include <cuda_runtime.h>
#include <cstdint>

// Problem constants
#define BB 4
#define HW (512*1024)       // pixels per batch image
#define NI 8                // instances 1..8
#define NBINS 32768
#define FBINS 32768.0f
#define WBIN (2.0f/(float)NBINS)
#define NTILE1 64
#define NSEG 8              // pass3 segments per row
#define SEGBINS (NBINS/NSEG)   // 4096
#define LAMBDA 0.72134752044448170f   // 0.5*log2(e)
#define INV1024 (1.0f/1024.0f)
#define KOFF 15.0f                    // log2(NBINS)

// ---------------- device scratch ----------------
__device__ unsigned int g_hist[NI*BB*2*NBINS];     // 8 MB: [n][b][pos][bin]
__device__ float g_part[NI][BB][NTILE1][6];        // pass1 partials (cnt,e0,e1,q0,q1,qq)
__device__ float g_coef[BB][NI][8];                // a0,b0,a1,b1,k,cnt,sl,(pad)
__device__ float g_fg[BB][NI];
__device__ float g_bg[BB][2];
__device__ float g_seg[NI*BB][NSEG][2];            // pass3a segment totals (pos,neg)
__device__ float g_lovj[NI*BB];                    // jacsum accumulators

// ---------------- fast tanh (Eigen-style rational, |err| ~1e-7) ----------------
__device__ __forceinline__ float tanh_fast(float x) {
    float xc = fminf(fmaxf(x, -7.99881172f), 7.99881172f);
    float x2 = xc * xc;
    float p = fmaf(x2, -2.76076847742355e-16f, 2.00018790482477e-13f);
    p = fmaf(x2, p, -8.60467152213735e-11f);
    p = fmaf(x2, p, 5.12229709037114e-08f);
    p = fmaf(x2, p, 1.48572235717979e-05f);
    p = fmaf(x2, p, 6.37261928875436e-04f);
    p = fmaf(x2, p, 4.89352455891786e-03f);
    p = p * xc;
    float q = fmaf(x2, 1.19825839466702e-06f, 1.18534705686654e-04f);
    q = fmaf(x2, q, 2.26843463243900e-03f);
    q = fmaf(x2, q, 4.89352518554385e-03f);
    return __fdividef(p, q);
}

// ---------------- pass 1: half 0 -> (cnt,e0,e1), half 1 -> (q0,q1,qq), all 8 instances ----------------
#define P1_TPB 512
#define P1_PPT 32   // per thread; each 256-thread half covers the same 8192-px tile

__global__ __launch_bounds__(P1_TPB)
void pass1_kernel(const float* __restrict__ xv, const float* __restrict__ xs,
                  const int* __restrict__ t) {
    const int b = blockIdx.y;
    const int bx = blockIdx.x;
    const int tid = threadIdx.x;
    const int grp = tid >> 8;               // 0: emb stats, 1: sigma stats
    const int l   = tid & 255;
    const float* xv0 = xv + (long)b*2*HW;
    const float* xv1 = xv0 + HW;
    const float* xs0 = xs + (long)b*2*HW;
    const float* xs1 = xs0 + HW;
    const int*   tp  = t + (long)b*HW;

    float a[NI][3];
    #pragma unroll
    for (int j = 0; j < NI; j++)
        #pragma unroll
        for (int i = 0; i < 3; i++) a[j][i] = 0.0f;

    const int p0 = bx * (256 * P1_PPT) + l;
    #pragma unroll 4
    for (int i = 0; i < P1_PPT; i++) {
        int p = p0 + i * 256;
        int tv = tp[p];
        if (tv > 0) {
            float s0, s1, s2;
            if (grp == 0) {                  // warp-uniform branch
                s0 = 1.0f;
                s1 = tanh_fast(xv0[p]) + (float)(p >> 10) * INV1024;
                s2 = tanh_fast(xv1[p]) + (float)(p & 1023) * INV1024;
            } else {
                float q0 = xs0[p], q1 = xs1[p];
                s0 = q0; s1 = q1; s2 = q0*q0 + q1*q1;
            }
            #pragma unroll
            for (int j = 0; j < NI; j++) {
                float m = (tv == j + 1) ? 1.0f : 0.0f;
                a[j][0] = fmaf(m, s0, a[j][0]);
                a[j][1] = fmaf(m, s1, a[j][1]);
                a[j][2] = fmaf(m, s2, a[j][2]);
            }
        }
    }
    // warp reduce 24 values
    #pragma unroll
    for (int off = 16; off; off >>= 1)
        #pragma unroll
        for (int j = 0; j < NI; j++)
            #pragma unroll
            for (int i = 0; i < 3; i++)
                a[j][i] += __shfl_down_sync(0xffffffffu, a[j][i], off);

    __shared__ float sacc[2][24];
    if (tid < 48) ((float*)sacc)[tid] = 0.0f;
    __syncthreads();
    if ((tid & 31) == 0) {
        #pragma unroll
        for (int j = 0; j < NI; j++)
            #pragma unroll
            for (int i = 0; i < 3; i++)
                atomicAdd(&sacc[grp][j*3+i], a[j][i]);
    }
    __syncthreads();
    if (tid < 48) {
        int g = tid / 24, r = tid % 24;
        g_part[r/3][b][bx][g*3 + r%3] = sacc[g][r];
    }

    // zero histogram: 131072 threads, 2097152 words -> 4 uint4 each, coalesced
    uint4 z = make_uint4(0u, 0u, 0u, 0u);
    uint4* h4 = (uint4*)g_hist;
    int gid = (b * NTILE1 + bx) * P1_TPB + tid;
    h4[gid]          = z;
    h4[gid + 131072] = z;
    h4[gid + 262144] = z;
    h4[gid + 393216] = z;
}

// ---------------- finalize: reduce partials -> coefficients + sigma loss ----------------
__global__ __launch_bounds__(1024)
void finalize_kernel() {
    int tid = threadIdx.x;
    int w = tid >> 5, l = tid & 31;     // 32 warps = 32 (n,b) rows
    int n = w >> 2, b = w & 3;
    float s[6];
    #pragma unroll
    for (int i = 0; i < 6; i++)
        s[i] = g_part[n][b][l][i] + g_part[n][b][l + 32][i];
    #pragma unroll
    for (int off = 16; off; off >>= 1)
        #pragma unroll
        for (int i = 0; i < 6; i++)
            s[i] += __shfl_down_sync(0xffffffffu, s[i], off);
    if (l == 0) {
        float cnt = s[0];
        float inv = 1.0f / fmaxf(cnt, 1.0f);
        float c0 = s[1]*inv, c1 = s[2]*inv, pp0 = s[3]*inv, pp1 = s[4]*inv;
        float ps0 = expf(10.0f * pp0), ps1 = expf(10.0f * pp1);
        g_coef[b][n][0] = -LAMBDA * ps0;
        g_coef[b][n][1] = 2.0f * LAMBDA * ps0 * c0;
        g_coef[b][n][2] = -LAMBDA * ps1;
        g_coef[b][n][3] = 2.0f * LAMBDA * ps1 * c1;
        g_coef[b][n][4] = KOFF - LAMBDA * (ps0*c0*c0 + ps1*c1*c1);
        g_coef[b][n][5] = cnt;
        // sigma loss closed form: (sum q^2)/safe - (cnt/safe)*(pp0^2+pp1^2)
        float sl = s[5]*inv - (cnt*inv) * (pp0*pp0 + pp1*pp1);
        g_coef[b][n][6] = fmaxf(sl, 0.0f);
    }
    if (tid < 32) { ((float*)g_fg)[tid] = 0.0f; g_lovj[tid] = 0.0f; }
    if (tid < 8)  ((float*)g_bg)[tid] = 0.0f;
}

// ---------------- pass 2: histograms + seed partials (round-9 scalar form) ----------------
#define P2_TPB 256
#define P2_PPT 8    // 2048 px/block -> 256 blocks/batch

__global__ __launch_bounds__(P2_TPB)
void pass2_kernel(const float* __restrict__ xv,
                  const float* __restrict__ xseed, const int* __restrict__ t) {
    const int b = blockIdx.y;
    const int tid = threadIdx.x;
    const int wid = tid >> 5;

    __shared__ float sa0[NI], sb0[NI], sa1[NI], sb1[NI], sk[NI];
    __shared__ float s_fg[8][NI+1];
    __shared__ float sbg[2];
    if (tid < NI) {
        sa0[tid] = g_coef[b][tid][0];
        sb0[tid] = g_coef[b][tid][1];
        sa1[tid] = g_coef[b][tid][2];
        sb1[tid] = g_coef[b][tid][3];
        sk[tid]  = g_coef[b][tid][4];
    }
    if (tid < 8*(NI+1)) ((float*)s_fg)[tid] = 0.0f;
    if (tid < 2) sbg[tid] = 0.0f;
    __syncthreads();

    const float* xv0 = xv + (long)b*2*HW;
    const float* xv1 = xv0 + HW;
    const float* sdp = xseed + (long)b*HW;
    const int*   tp  = t + (long)b*HW;

    float bgc = 0.0f, bgs = 0.0f;
    const int p0 = blockIdx.x * (P2_TPB * P2_PPT) + tid;

    for (int i = 0; i < P2_PPT; i++) {
        int p = p0 + i * P2_TPB;
        int tv = tp[p];
        float e0 = tanh_fast(xv0[p]) + (float)(p >> 10) * INV1024;
        float e1 = tanh_fast(xv1[p]) + (float)(p & 1023) * INV1024;
        float E0 = e0*e0, E1 = e1*e1;
        float sd = fmaf(tanh_fast(0.5f * sdp[p]), 0.5f, 0.5f);
        float isbg = (tv == 0) ? 1.0f : 0.0f;
        bgc += isbg;
        bgs = fmaf(isbg, sd*sd, bgs);

        float yown = 0.0f;
        #pragma unroll
        for (int n = 0; n < NI; n++) {
            // u = KOFF - 0.5*log2e * dist   ->  y = 2^u = NBINS * gauss
            float u = fmaf(sa0[n], E0, fmaf(sb0[n], e0, fmaf(sa1[n], E1, fmaf(sb1[n], e1, sk[n]))));
            float um = fmaxf(u, -2.0f);
            float fr = um + 12582912.0f;           // round-to-nearest int
            float f  = um - (fr - 12582912.0f);    // f in [-0.5, 0.5]
            int   ib = __float_as_int(fr);
            float scale = __int_as_float((ib + (127 - 0x4B400000)) << 23); // 2^i
            float pe = fmaf(f, 1.33335581e-3f, 9.61812911e-3f);
            pe = fmaf(f, pe, 5.55041087e-2f);
            pe = fmaf(f, pe, 2.40226507e-1f);
            pe = fmaf(f, pe, 6.93147181e-1f);
            pe = fmaf(f, pe, 1.0f);
            float y = pe * scale;                  // = NBINS*gauss
            bool pos = (tv == n + 1);
            if (pos) yown = y;
            float binf = pos ? (FBINS - y) : y;    // err * BSCALE
            int bin = (int)binf;
            bin = min(bin, NBINS - 1);
            bin = max(bin, 0);
            int off = ((n*BB + b)*2 + (pos ? 1 : 0))*NBINS + bin;
            atomicAdd(&g_hist[off], 1u);
        }
        // own-instance seed fg term via tv-indexed smem atomic
        float fgd = fmaf(yown, -(1.0f/FBINS), sd);
        if (tv > 0)
            atomicAdd(&s_fg[wid][tv], fgd * fgd);
    }
    __syncthreads();

    // bg reduce
    #pragma unroll
    for (int off = 16; off; off >>= 1) {
        bgc += __shfl_down_sync(0xffffffffu, bgc, off);
        bgs += __shfl_down_sync(0xffffffffu, bgs, off);
    }
    if ((tid & 31) == 0) {
        atomicAdd(&sbg[0], bgc);
        atomicAdd(&sbg[1], bgs);
    }
    // fg block reduce -> global
    if (tid >= 32 && tid < 32 + NI) {
        int n = tid - 32;
        float sfg = 0.0f;
        #pragma unroll
        for (int w = 0; w < 8; w++) sfg += s_fg[w][n+1];
        atomicAdd(&g_fg[b][n], sfg);
    }
    __syncthreads();
    if (tid == 0) {
        atomicAdd(&g_bg[b][0], sbg[0]);
        atomicAdd(&g_bg[b][1], sbg[1]);
    }
}

// ---------------- pass 3a: per (row, segment) totals ----------------
#define P3_TPB 1024

__global__ __launch_bounds__(P3_TPB)
void pass3a_kernel() {
    const int seg = blockIdx.x;    // 0..7
    const int row = blockIdx.y;    // 0..31 = n*BB+b
    const int j = threadIdx.x;
    const int lane = j & 31;
    const int wrp = j >> 5;
    const uint4* hp4 = (const uint4*)(g_hist + (long)(row*2 + 1)*NBINS) + seg*(SEGBINS/4);
    const uint4* hn4 = (const uint4*)(g_hist + (long)(row*2 + 0)*NBINS) + seg*(SEGBINS/4);

    uint4 v = hp4[j];
    uint4 w = hn4[j];
    float tp = (float)v.x + (float)v.y + (float)v.z + (float)v.w;
    float tn = (float)w.x + (float)w.y + (float)w.z + (float)w.w;
    #pragma unroll
    for (int off = 16; off; off >>= 1) {
        tp += __shfl_down_sync(0xffffffffu, tp, off);
        tn += __shfl_down_sync(0xffffffffu, tn, off);
    }
    __shared__ float swp[32], swn[32];
    if (lane == 0) { swp[wrp] = tp; swn[wrp] = tn; }
    __syncthreads();
    if (wrp == 0) {
        float ap = swp[lane], an = swn[lane];
        #pragma unroll
        for (int off = 16; off; off >>= 1) {
            ap += __shfl_down_sync(0xffffffffu, ap, off);
            an += __shfl_down_sync(0xffffffffu, an, off);
        }
        if (lane == 0) { g_seg[row][seg][0] = ap; g_seg[row][seg][1] = an; }
    }
}

// ---------------- pass 3b: suffix walk per segment -> jacsum atomics ----------------
__global__ __launch_bounds__(P3_TPB)
void pass3b_kernel() {
    const int seg = blockIdx.x;    // 0..7
    const int row = blockIdx.y;    // 0..31
    const int n = row >> 2;
    const int b = row & 3;
    const int j = threadIdx.x;
    const int lane = j & 31;
    const int wrp = j >> 5;

    const float G = g_coef[b][n][5];   // total positives = instance pixel count
    if (G <= 0.0f) return;

    const uint4* hp4 = (const uint4*)(g_hist + (long)(row*2 + 1)*NBINS) + seg*(SEGBINS/4);
    const uint4* hn4 = (const uint4*)(g_hist + (long)(row*2 + 0)*NBINS) + seg*(SEGBINS/4);

    // segment-exclusive suffix (segments after this one)
    float C0 = 0.0f, D0 = 0.0f;
    #pragma unroll
    for (int s2 = 0; s2 < NSEG; s2++)
        if (s2 > seg) { C0 += g_seg[row][s2][0]; D0 += g_seg[row][s2][1]; }

    uint4 v = hp4[j];
    uint4 w = hn4[j];
    float p[4] = {(float)v.x, (float)v.y, (float)v.z, (float)v.w};
    float nn[4] = {(float)w.x, (float)w.y, (float)w.z, (float)w.w};
    float tp = p[0] + p[1] + p[2] + p[3];
    float tn = nn[0] + nn[1] + nn[2] + nn[3];

    // warp inclusive suffix scan over thread totals
    float sp = tp, sn = tn;
    #pragma unroll
    for (int off = 1; off < 32; off <<= 1) {
        float a = __shfl_down_sync(0xffffffffu, sp, off);
        float c = __shfl_down_sync(0xffffffffu, sn, off);
        if (lane + off < 32) { sp += a; sn += c; }
    }
    __shared__ float swp[32], swn[32], sep[32], sen[32];
    __shared__ float s_jacsum;
    if (lane == 0) { swp[wrp] = sp; swn[wrp] = sn; }
    if (j == 0) s_jacsum = 0.0f;
    __syncthreads();
    if (wrp == 0) {
        float wp = swp[lane], wn = swn[lane];
        float ip = wp, in_ = wn;
        #pragma unroll
        for (int off = 1; off < 32; off <<= 1) {
            float a = __shfl_down_sync(0xffffffffu, ip, off);
            float c = __shfl_down_sync(0xffffffffu, in_, off);
            if (lane + off < 32) { ip += a; in_ += c; }
        }
        sep[lane] = ip - wp;    // exclusive suffix (warps after)
        sen[lane] = in_ - wn;
    }
    __syncthreads();

    float C = C0 + sep[wrp] + (sp - tp);
    float D = D0 + sen[wrp] + (sn - tn);
    float jacsum = 0.0f;
    #pragma unroll
    for (int k = 3; k >= 0; k--) {
        C += p[k];
        D += nn[k];
        float jac = 1.0f - __fdividef(G - C, G + D);
        if (seg*SEGBINS + j*4 + k >= 1) jacsum += jac;
    }
    #pragma unroll
    for (int off = 16; off; off >>= 1)
        jacsum += __shfl_down_sync(0xffffffffu, jacsum, off);
    if (lane == 0) atomicAdd(&s_jacsum, jacsum);
    __syncthreads();
    if (j == 0) atomicAdd(&g_lovj[row], s_jacsum);
}

// ---------------- final assembly ----------------
__global__ void final_kernel(float* __restrict__ out) {
    __shared__ float parts[BB];
    int b = threadIdx.x;
    if (b < BB) {
        float npres = 0.0f, lovs = 0.0f, sls = 0.0f, fgs = 0.0f;
        #pragma unroll
        for (int n = 0; n < NI; n++) {
            float cnt = g_coef[b][n][5];
            float pres = (cnt > 0.0f) ? 1.0f : 0.0f;
            float inv = 1.0f / fmaxf(cnt, 1.0f);
            npres += pres;
            lovs += pres * WBIN * (0.5f + g_lovj[n*BB + b]);
            sls  += pres * g_coef[b][n][6];
            fgs  += pres * g_fg[b][n] * inv;
        }
        float np = fmaxf(npres, 1.0f);
        float bgc = fmaxf(g_bg[b][0], 1.0f);
        float bgl = g_bg[b][1] / bgc;
        parts[b] = lovs / np + sls / np + (bgl + fgs) / (1.0f + npres);
    }
    __syncthreads();
    if (threadIdx.x == 0)
        out[0] = (parts[0] + parts[1] + parts[2] + parts[3]) * 0.25f;
}

// ---------------- launch ----------------
extern "C" void kernel_launch(void* const* d_in, const int* in_sizes, int n_in,
                              void* d_out, int out_size) {
    const float* xv    = (const float*)d_in[0];   // [4,2,512,1024]
    const float* xs    = (const float*)d_in[1];   // [4,2,512,1024]
    const float* xseed = (const float*)d_in[2];   // [4,1,512,1024]
    const int*   t     = (const int*)d_in[3];     // [4,512,1024]
    float* out = (float*)d_out;

    dim3 g1(NTILE1, BB);                   // (64, 4)
    pass1_kernel<<<g1, P1_TPB>>>(xv, xs, t);

    finalize_kernel<<<1, 1024>>>();

    dim3 g2(HW / (P2_TPB * P2_PPT), BB);   // (256, 4)
    pass2_kernel<<<g2, P2_TPB>>>(xv, xseed, t);

    dim3 g3(NSEG, NI * BB);                // (8, 32)
    pass3a_kernel<<<g3, P3_TPB>>>();
    pass3b_kernel<<<g3, P3_TPB>>>();

    final_kernel<<<1, 32>>>(out);
}

// round 15
// speedup vs baseline: 1.0418x; 1.0418x over previous
#include <cuda_runtime.h>
#include <cstdint>

// Problem constants
#define BB 4
#define HW (512*1024)       // pixels per batch image
#define NI 8                // instances 1..8
#define NBINS 32768
#define FBINS 32768.0f
#define WBIN (2.0f/(float)NBINS)
#define NTILE1 64
#define NSEG 8              // pass3 segments per row
#define SEGBINS (NBINS/NSEG)   // 4096
#define LAMBDA 0.72134752044448170f   // 0.5*log2(e)
#define INV1024 (1.0f/1024.0f)
#define KOFF 15.0f                    // log2(NBINS)

// ---------------- device scratch ----------------
__device__ unsigned int g_hist[NI*BB*2*NBINS];     // 8 MB: [n][b][pos][bin]
__device__ float g_part[NI][BB][NTILE1][6];        // pass1 partials (cnt,e0,e1,q0,q1,qq)
__device__ float g_coef[BB][NI][8];                // a0,b0,a1,b1,k,cnt,sl,(pad)
__device__ float g_fg[BB][NI];
__device__ float g_bg[BB][2];
__device__ float g_seg[NI*BB][NSEG][2];            // pass3a segment totals (pos,neg)
__device__ float g_lovj[NI*BB];                    // jacsum accumulators
__device__ unsigned int g_done;                    // pass3b completion counter

// ---------------- fast tanh (Eigen-style rational, |err| ~1e-7) ----------------
__device__ __forceinline__ float tanh_fast(float x) {
    float xc = fminf(fmaxf(x, -7.99881172f), 7.99881172f);
    float x2 = xc * xc;
    float p = fmaf(x2, -2.76076847742355e-16f, 2.00018790482477e-13f);
    p = fmaf(x2, p, -8.60467152213735e-11f);
    p = fmaf(x2, p, 5.12229709037114e-08f);
    p = fmaf(x2, p, 1.48572235717979e-05f);
    p = fmaf(x2, p, 6.37261928875436e-04f);
    p = fmaf(x2, p, 4.89352455891786e-03f);
    p = p * xc;
    float q = fmaf(x2, 1.19825839466702e-06f, 1.18534705686654e-04f);
    q = fmaf(x2, q, 2.26843463243900e-03f);
    q = fmaf(x2, q, 4.89352518554385e-03f);
    return __fdividef(p, q);
}

// ---------------- pass 1: two halves of the block handle the two instance groups ----------------
#define P1_TPB 512
#define P1_PPT 32   // per thread; each 256-thread half covers the same 8192-px tile

__global__ __launch_bounds__(P1_TPB)
void pass1_kernel(const float* __restrict__ xv, const float* __restrict__ xs,
                  const int* __restrict__ t) {
    const int b = blockIdx.y;
    const int bx = blockIdx.x;
    const int tid = threadIdx.x;
    const int grp = tid >> 8;               // 0: instances 1-4, 1: instances 5-8
    const int l   = tid & 255;
    const float* xv0 = xv + (long)b*2*HW;
    const float* xv1 = xv0 + HW;
    const float* xs0 = xs + (long)b*2*HW;
    const float* xs1 = xs0 + HW;
    const int*   tp  = t + (long)b*HW;

    float a[4][6];
    #pragma unroll
    for (int j = 0; j < 4; j++)
        #pragma unroll
        for (int i = 0; i < 6; i++) a[j][i] = 0.0f;

    const int p0 = bx * (256 * P1_PPT) + l;
    #pragma unroll 4
    for (int i = 0; i < P1_PPT; i++) {
        int p = p0 + i * 256;
        int tv = tp[p];
        unsigned rel = (unsigned)(tv - 1 - 4*grp);
        if (rel < 4u) {
            float e0 = tanh_fast(xv0[p]) + (float)(p >> 10) * INV1024;
            float e1 = tanh_fast(xv1[p]) + (float)(p & 1023) * INV1024;
            float q0 = xs0[p], q1 = xs1[p];
            float qq = q0*q0 + q1*q1;
            #pragma unroll
            for (int j = 0; j < 4; j++) {
                float m = (rel == (unsigned)j) ? 1.0f : 0.0f;
                a[j][0] += m;
                a[j][1] = fmaf(m, e0, a[j][1]);
                a[j][2] = fmaf(m, e1, a[j][2]);
                a[j][3] = fmaf(m, q0, a[j][3]);
                a[j][4] = fmaf(m, q1, a[j][4]);
                a[j][5] = fmaf(m, qq, a[j][5]);
            }
        }
    }
    // warp reduce 24 values
    #pragma unroll
    for (int off = 16; off; off >>= 1)
        #pragma unroll
        for (int j = 0; j < 4; j++)
            #pragma unroll
            for (int i = 0; i < 6; i++)
                a[j][i] += __shfl_down_sync(0xffffffffu, a[j][i], off);

    __shared__ float sacc[2][24];
    if (tid < 48) ((float*)sacc)[tid] = 0.0f;
    __syncthreads();
    if ((tid & 31) == 0) {
        #pragma unroll
        for (int j = 0; j < 4; j++)
            #pragma unroll
            for (int i = 0; i < 6; i++)
                atomicAdd(&sacc[grp][j*6+i], a[j][i]);
    }
    __syncthreads();
    if (tid < 48) {
        int g = tid / 24, r = tid % 24;
        g_part[4*g + r/6][b][bx][r % 6] = sacc[g][r];
    }

    // zero histogram: 131072 threads, 2097152 words -> 4 uint4 each, coalesced
    uint4 z = make_uint4(0u, 0u, 0u, 0u);
    uint4* h4 = (uint4*)g_hist;
    int gid = (b * NTILE1 + bx) * P1_TPB + tid;
    h4[gid]          = z;
    h4[gid + 131072] = z;
    h4[gid + 262144] = z;
    h4[gid + 393216] = z;
}

// ---------------- finalize: reduce partials -> coefficients + sigma loss ----------------
__global__ __launch_bounds__(1024)
void finalize_kernel() {
    int tid = threadIdx.x;
    int w = tid >> 5, l = tid & 31;     // 32 warps = 32 (n,b) rows
    int n = w >> 2, b = w & 3;
    float s[6];
    #pragma unroll
    for (int i = 0; i < 6; i++)
        s[i] = g_part[n][b][l][i] + g_part[n][b][l + 32][i];
    #pragma unroll
    for (int off = 16; off; off >>= 1)
        #pragma unroll
        for (int i = 0; i < 6; i++)
            s[i] += __shfl_down_sync(0xffffffffu, s[i], off);
    if (l == 0) {
        float cnt = s[0];
        float inv = 1.0f / fmaxf(cnt, 1.0f);
        float c0 = s[1]*inv, c1 = s[2]*inv, pp0 = s[3]*inv, pp1 = s[4]*inv;
        float ps0 = expf(10.0f * pp0), ps1 = expf(10.0f * pp1);
        g_coef[b][n][0] = -LAMBDA * ps0;
        g_coef[b][n][1] = 2.0f * LAMBDA * ps0 * c0;
        g_coef[b][n][2] = -LAMBDA * ps1;
        g_coef[b][n][3] = 2.0f * LAMBDA * ps1 * c1;
        g_coef[b][n][4] = KOFF - LAMBDA * (ps0*c0*c0 + ps1*c1*c1);
        g_coef[b][n][5] = cnt;
        // sigma loss closed form: (sum q^2)/safe - (cnt/safe)*(pp0^2+pp1^2)
        float sl = s[5]*inv - (cnt*inv) * (pp0*pp0 + pp1*pp1);
        g_coef[b][n][6] = fmaxf(sl, 0.0f);
    }
    if (tid < 32) { ((float*)g_fg)[tid] = 0.0f; g_lovj[tid] = 0.0f; }
    if (tid < 8)  ((float*)g_bg)[tid] = 0.0f;
    if (tid == 0) g_done = 0u;
}

// ---------------- pass 2: histograms + seed partials (round-9 body, more blocks) ----------------
#define P2_TPB 256
#define P2_PPT 4    // 1024 px/block -> 512 blocks/batch

__global__ __launch_bounds__(P2_TPB)
void pass2_kernel(const float* __restrict__ xv,
                  const float* __restrict__ xseed, const int* __restrict__ t) {
    const int b = blockIdx.y;
    const int tid = threadIdx.x;
    const int wid = tid >> 5;

    __shared__ float sa0[NI], sb0[NI], sa1[NI], sb1[NI], sk[NI];
    __shared__ float s_fg[8][NI+1];
    __shared__ float sbg[2];
    if (tid < NI) {
        sa0[tid] = g_coef[b][tid][0];
        sb0[tid] = g_coef[b][tid][1];
        sa1[tid] = g_coef[b][tid][2];
        sb1[tid] = g_coef[b][tid][3];
        sk[tid]  = g_coef[b][tid][4];
    }
    if (tid < 8*(NI+1)) ((float*)s_fg)[tid] = 0.0f;
    if (tid < 2) sbg[tid] = 0.0f;
    __syncthreads();

    const float* xv0 = xv + (long)b*2*HW;
    const float* xv1 = xv0 + HW;
    const float* sdp = xseed + (long)b*HW;
    const int*   tp  = t + (long)b*HW;

    float bgc = 0.0f, bgs = 0.0f;
    const int p0 = blockIdx.x * (P2_TPB * P2_PPT) + tid;

    for (int i = 0; i < P2_PPT; i++) {
        int p = p0 + i * P2_TPB;
        int tv = tp[p];
        float e0 = tanh_fast(xv0[p]) + (float)(p >> 10) * INV1024;
        float e1 = tanh_fast(xv1[p]) + (float)(p & 1023) * INV1024;
        float E0 = e0*e0, E1 = e1*e1;
        float sd = fmaf(tanh_fast(0.5f * sdp[p]), 0.5f, 0.5f);
        float isbg = (tv == 0) ? 1.0f : 0.0f;
        bgc += isbg;
        bgs = fmaf(isbg, sd*sd, bgs);

        float yown = 0.0f;
        #pragma unroll
        for (int n = 0; n < NI; n++) {
            // u = KOFF - 0.5*log2e * dist   ->  y = 2^u = NBINS * gauss
            float u = fmaf(sa0[n], E0, fmaf(sb0[n], e0, fmaf(sa1[n], E1, fmaf(sb1[n], e1, sk[n]))));
            float um = fmaxf(u, -2.0f);
            float fr = um + 12582912.0f;           // round-to-nearest int
            float f  = um - (fr - 12582912.0f);    // f in [-0.5, 0.5]
            int   ib = __float_as_int(fr);
            float scale = __int_as_float((ib + (127 - 0x4B400000)) << 23); // 2^i
            float pe = fmaf(f, 1.33335581e-3f, 9.61812911e-3f);
            pe = fmaf(f, pe, 5.55041087e-2f);
            pe = fmaf(f, pe, 2.40226507e-1f);
            pe = fmaf(f, pe, 6.93147181e-1f);
            pe = fmaf(f, pe, 1.0f);
            float y = pe * scale;                  // = NBINS*gauss
            bool pos = (tv == n + 1);
            if (pos) yown = y;
            float binf = pos ? (FBINS - y) : y;    // err * BSCALE
            int bin = (int)binf;
            bin = min(bin, NBINS - 1);
            bin = max(bin, 0);
            int off = ((n*BB + b)*2 + (pos ? 1 : 0))*NBINS + bin;
            atomicAdd(&g_hist[off], 1u);
        }
        // own-instance seed fg term via tv-indexed smem atomic
        float fgd = fmaf(yown, -(1.0f/FBINS), sd);
        if (tv > 0)
            atomicAdd(&s_fg[wid][tv], fgd * fgd);
    }
    __syncthreads();

    // bg reduce
    #pragma unroll
    for (int off = 16; off; off >>= 1) {
        bgc += __shfl_down_sync(0xffffffffu, bgc, off);
        bgs += __shfl_down_sync(0xffffffffu, bgs, off);
    }
    if ((tid & 31) == 0) {
        atomicAdd(&sbg[0], bgc);
        atomicAdd(&sbg[1], bgs);
    }
    // fg block reduce -> global
    if (tid >= 32 && tid < 32 + NI) {
        int n = tid - 32;
        float sfg = 0.0f;
        #pragma unroll
        for (int w = 0; w < 8; w++) sfg += s_fg[w][n+1];
        atomicAdd(&g_fg[b][n], sfg);
    }
    __syncthreads();
    if (tid == 0) {
        atomicAdd(&g_bg[b][0], sbg[0]);
        atomicAdd(&g_bg[b][1], sbg[1]);
    }
}

// ---------------- pass 3a: per (row, segment) totals ----------------
#define P3_TPB 1024

__global__ __launch_bounds__(P3_TPB)
void pass3a_kernel() {
    const int seg = blockIdx.x;    // 0..7
    const int row = blockIdx.y;    // 0..31 = n*BB+b
    const int j = threadIdx.x;
    const int lane = j & 31;
    const int wrp = j >> 5;
    const uint4* hp4 = (const uint4*)(g_hist + (long)(row*2 + 1)*NBINS) + seg*(SEGBINS/4);
    const uint4* hn4 = (const uint4*)(g_hist + (long)(row*2 + 0)*NBINS) + seg*(SEGBINS/4);

    uint4 v = hp4[j];
    uint4 w = hn4[j];
    float tp = (float)v.x + (float)v.y + (float)v.z + (float)v.w;
    float tn = (float)w.x + (float)w.y + (float)w.z + (float)w.w;
    #pragma unroll
    for (int off = 16; off; off >>= 1) {
        tp += __shfl_down_sync(0xffffffffu, tp, off);
        tn += __shfl_down_sync(0xffffffffu, tn, off);
    }
    __shared__ float swp[32], swn[32];
    if (lane == 0) { swp[wrp] = tp; swn[wrp] = tn; }
    __syncthreads();
    if (wrp == 0) {
        float ap = swp[lane], an = swn[lane];
        #pragma unroll
        for (int off = 16; off; off >>= 1) {
            ap += __shfl_down_sync(0xffffffffu, ap, off);
            an += __shfl_down_sync(0xffffffffu, an, off);
        }
        if (lane == 0) { g_seg[row][seg][0] = ap; g_seg[row][seg][1] = an; }
    }
}

// ---------------- pass 3b: suffix walk per segment -> jacsum atomics + fused final ----------------
__global__ __launch_bounds__(P3_TPB)
void pass3b_kernel(float* __restrict__ out) {
    const int seg = blockIdx.x;    // 0..7
    const int row = blockIdx.y;    // 0..31
    const int n = row >> 2;
    const int b = row & 3;
    const int j = threadIdx.x;
    const int lane = j & 31;
    const int wrp = j >> 5;

    const float G = g_coef[b][n][5];   // total positives = instance pixel count
    const bool active = (G > 0.0f);

    __shared__ float swp[32], swn[32], sep[32], sen[32];
    __shared__ float s_jacsum;
    __shared__ unsigned int s_last;

    if (active) {
        const uint4* hp4 = (const uint4*)(g_hist + (long)(row*2 + 1)*NBINS) + seg*(SEGBINS/4);
        const uint4* hn4 = (const uint4*)(g_hist + (long)(row*2 + 0)*NBINS) + seg*(SEGBINS/4);

        // segment-exclusive suffix (segments after this one)
        float C0 = 0.0f, D0 = 0.0f;
        #pragma unroll
        for (int s2 = 0; s2 < NSEG; s2++)
            if (s2 > seg) { C0 += g_seg[row][s2][0]; D0 += g_seg[row][s2][1]; }

        uint4 v = hp4[j];
        uint4 w = hn4[j];
        float p[4] = {(float)v.x, (float)v.y, (float)v.z, (float)v.w};
        float nn[4] = {(float)w.x, (float)w.y, (float)w.z, (float)w.w};
        float tp = p[0] + p[1] + p[2] + p[3];
        float tn = nn[0] + nn[1] + nn[2] + nn[3];

        // warp inclusive suffix scan over thread totals
        float sp = tp, sn = tn;
        #pragma unroll
        for (int off = 1; off < 32; off <<= 1) {
            float a = __shfl_down_sync(0xffffffffu, sp, off);
            float c = __shfl_down_sync(0xffffffffu, sn, off);
            if (lane + off < 32) { sp += a; sn += c; }
        }
        if (lane == 0) { swp[wrp] = sp; swn[wrp] = sn; }
        if (j == 0) s_jacsum = 0.0f;
        __syncthreads();
        if (wrp == 0) {
            float wp = swp[lane], wn = swn[lane];
            float ip = wp, in_ = wn;
            #pragma unroll
            for (int off = 1; off < 32; off <<= 1) {
                float a = __shfl_down_sync(0xffffffffu, ip, off);
                float c = __shfl_down_sync(0xffffffffu, in_, off);
                if (lane + off < 32) { ip += a; in_ += c; }
            }
            sep[lane] = ip - wp;    // exclusive suffix (warps after)
            sen[lane] = in_ - wn;
        }
        __syncthreads();

        float C = C0 + sep[wrp] + (sp - tp);
        float D = D0 + sen[wrp] + (sn - tn);
        float jacsum = 0.0f;
        #pragma unroll
        for (int k = 3; k >= 0; k--) {
            C += p[k];
            D += nn[k];
            float jac = 1.0f - __fdividef(G - C, G + D);
            if (seg*SEGBINS + j*4 + k >= 1) jacsum += jac;
        }
        #pragma unroll
        for (int off = 16; off; off >>= 1)
            jacsum += __shfl_down_sync(0xffffffffu, jacsum, off);
        if (lane == 0) atomicAdd(&s_jacsum, jacsum);
        __syncthreads();
        if (j == 0) atomicAdd(&g_lovj[row], s_jacsum);
    }

    // completion counter (ALL blocks arrive, active or not)
    if (j == 0) {
        __threadfence();
        unsigned old = atomicAdd(&g_done, 1u);
        s_last = (old == (unsigned)(NSEG * NI * BB - 1)) ? 1u : 0u;
    }
    __syncthreads();

    // last block assembles the final scalar
    if (s_last && wrp == 0) {
        float part = 0.0f;
        if (lane < BB) {
            int bb = lane;
            float npres = 0.0f, lovs = 0.0f, sls = 0.0f, fgs = 0.0f;
            #pragma unroll
            for (int m = 0; m < NI; m++) {
                float cnt = g_coef[bb][m][5];
                float pres = (cnt > 0.0f) ? 1.0f : 0.0f;
                float inv = 1.0f / fmaxf(cnt, 1.0f);
                npres += pres;
                lovs += pres * WBIN * (0.5f + g_lovj[m*BB + bb]);
                sls  += pres * g_coef[bb][m][6];
                fgs  += pres * g_fg[bb][m] * inv;
            }
            float np = fmaxf(npres, 1.0f);
            float bgc = fmaxf(g_bg[bb][0], 1.0f);
            float bgl = g_bg[bb][1] / bgc;
            part = lovs / np + sls / np + (bgl + fgs) / (1.0f + npres);
        }
        #pragma unroll
        for (int off = 2; off; off >>= 1)
            part += __shfl_down_sync(0xffffffffu, part, off);
        if (lane == 0) out[0] = part * 0.25f;
    }
}

// ---------------- launch ----------------
extern "C" void kernel_launch(void* const* d_in, const int* in_sizes, int n_in,
                              void* d_out, int out_size) {
    const float* xv    = (const float*)d_in[0];   // [4,2,512,1024]
    const float* xs    = (const float*)d_in[1];   // [4,2,512,1024]
    const float* xseed = (const float*)d_in[2];   // [4,1,512,1024]
    const int*   t     = (const int*)d_in[3];     // [4,512,1024]
    float* out = (float*)d_out;

    dim3 g1(NTILE1, BB);                   // (64, 4)
    pass1_kernel<<<g1, P1_TPB>>>(xv, xs, t);

    finalize_kernel<<<1, 1024>>>();

    dim3 g2(HW / (P2_TPB * P2_PPT), BB);   // (512, 4)
    pass2_kernel<<<g2, P2_TPB>>>(xv, xseed, t);

    dim3 g3(NSEG, NI * BB);                // (8, 32)
    pass3a_kernel<<<g3, P3_TPB>>>();
    pass3b_kernel<<<g3, P3_TPB>>>(out);
}